// round 1
// baseline (speedup 1.0000x reference)
#include <cuda_runtime.h>
#include <math.h>

// Problem constants
#define BB 2
#define TT 2048
#define HH 16
#define DD 64
#define CC 1024
#define MM (BB*TT)   // 4096

// Scratch (allocation-free rule: __device__ globals)
__device__ float g_q[MM*CC];
__device__ float g_k[MM*CC];
__device__ float g_v[MM*CC];
__device__ float g_att[MM*CC];

// ---------------------------------------------------------------------------
// Generic SGEMM: out[m,n] = sum_k A[m,k] * W[n,k] + bias[n]
// M=4096, N=1024, K=1024. Tiles: BM=BN=128, BK=8, 256 threads, 8x8 microtile.
// ---------------------------------------------------------------------------
__device__ __forceinline__ void sgemm_body(
    const float* __restrict__ A, const float* __restrict__ W,
    const float* __restrict__ bias, float* __restrict__ out)
{
    const int K = 1024, N = 1024;
    const int BM = 128, BN = 128, BK = 8;
    __shared__ float As[BK][BM];
    __shared__ float Bs[BK][BN];

    int tid = threadIdx.x;
    int tx = tid & 15;        // 0..15 -> output cols
    int ty = tid >> 4;        // 0..15 -> output rows
    int m0 = blockIdx.y * BM;
    int n0 = blockIdx.x * BN;

    float acc[8][8];
#pragma unroll
    for (int i = 0; i < 8; i++)
#pragma unroll
        for (int j = 0; j < 8; j++) acc[i][j] = 0.f;

    int lr = tid >> 1;        // 0..127
    int lc = (tid & 1) * 4;   // 0 or 4
    const float* Aptr = A + (m0 + lr) * K + lc;
    const float* Wptr = W + (n0 + lr) * K + lc;

    for (int k0 = 0; k0 < K; k0 += BK) {
        float4 av = *(const float4*)(Aptr + k0);
        float4 wv = *(const float4*)(Wptr + k0);
        As[lc+0][lr] = av.x; As[lc+1][lr] = av.y;
        As[lc+2][lr] = av.z; As[lc+3][lr] = av.w;
        Bs[lc+0][lr] = wv.x; Bs[lc+1][lr] = wv.y;
        Bs[lc+2][lr] = wv.z; Bs[lc+3][lr] = wv.w;
        __syncthreads();

#pragma unroll
        for (int kk = 0; kk < BK; kk++) {
            float4 a0 = *(const float4*)&As[kk][ty*8];
            float4 a1 = *(const float4*)&As[kk][ty*8+4];
            float4 b0 = *(const float4*)&Bs[kk][tx*8];
            float4 b1 = *(const float4*)&Bs[kk][tx*8+4];
            float af[8] = {a0.x,a0.y,a0.z,a0.w,a1.x,a1.y,a1.z,a1.w};
            float bf[8] = {b0.x,b0.y,b0.z,b0.w,b1.x,b1.y,b1.z,b1.w};
#pragma unroll
            for (int i = 0; i < 8; i++)
#pragma unroll
                for (int j = 0; j < 8; j++)
                    acc[i][j] += af[i] * bf[j];
        }
        __syncthreads();
    }

    float bb[8];
#pragma unroll
    for (int j = 0; j < 8; j++) bb[j] = bias[n0 + tx*8 + j];

#pragma unroll
    for (int i = 0; i < 8; i++) {
        int row = m0 + ty*8 + i;
        float* orow = out + (size_t)row * N + n0 + tx*8;
        float4 r0, r1;
        r0.x = acc[i][0] + bb[0]; r0.y = acc[i][1] + bb[1];
        r0.z = acc[i][2] + bb[2]; r0.w = acc[i][3] + bb[3];
        r1.x = acc[i][4] + bb[4]; r1.y = acc[i][5] + bb[5];
        r1.z = acc[i][6] + bb[6]; r1.w = acc[i][7] + bb[7];
        *(float4*)(orow)     = r0;
        *(float4*)(orow + 4) = r1;
    }
}

// QKV: gridDim.z selects which projection; writes scratch globals.
__global__ __launch_bounds__(256)
void sgemm_qkv_kernel(const float* __restrict__ x,
                      const float* __restrict__ Wq, const float* __restrict__ bq,
                      const float* __restrict__ Wk, const float* __restrict__ bk,
                      const float* __restrict__ Wv, const float* __restrict__ bv)
{
    const float* W; const float* b; float* out;
    if (blockIdx.z == 0)      { W = Wq; b = bq; out = g_q; }
    else if (blockIdx.z == 1) { W = Wk; b = bk; out = g_k; }
    else                      { W = Wv; b = bv; out = g_v; }
    sgemm_body(x, W, b, out);
}

// Output projection: reads g_att, writes d_out.
__global__ __launch_bounds__(256)
void sgemm_proj_kernel(const float* __restrict__ Wp, const float* __restrict__ bp,
                       float* __restrict__ out)
{
    sgemm_body(g_att, Wp, bp, out);
}

// ---------------------------------------------------------------------------
// RoPE applied in-place to g_q and g_k. Layout [B,T,H,D]; one thread per
// (tensor, b, t, h, j<32) rotation pair.
// ---------------------------------------------------------------------------
#define NPAIR (BB*TT*HH*32)   // 2*2048*16*32 = 2097152

__global__ __launch_bounds__(256)
void rope_kernel()
{
    int idx = blockIdx.x * blockDim.x + threadIdx.x;
    if (idx >= 2 * NPAIR) return;
    float* arr = (idx < NPAIR) ? g_q : g_k;
    int i = (idx < NPAIR) ? idx : idx - NPAIR;
    int j = i & 31;
    int h = (i >> 5) & 15;
    int t = (i >> 9) & 2047;
    int b = i >> 20;
    // inv_freq = 10000^(-j/32) = 2^(-j*log2(10000)/32)
    const float L = 13.287712379549449f / 32.0f;  // log2(10000)/32
    float inv = exp2f(-(float)j * L);
    float ang = (float)t * inv;
    float c, s;
    sincosf(ang, &s, &c);
    float* p = arr + (((size_t)(b*TT + t))*HH + h) * DD;
    float x1 = p[j];
    float x2 = p[j + 32];
    p[j]      = x1 * c - x2 * s;
    p[j + 32] = x2 * c + x1 * s;
}

// ---------------------------------------------------------------------------
// Causal flash attention, fp32. One thread per query row (128 rows/block).
// K/V staged in smem in 64-key tiles. Online softmax, acc[64] in registers.
// q,k,v layout: [B,T,H,D]; output g_att layout: [B,T,C] (= [B,T,H,D]).
// ---------------------------------------------------------------------------
__global__ __launch_bounds__(128, 1)
void attn_kernel()
{
    __shared__ float Ks[64][64];
    __shared__ float Vs[64][64];

    int tid = threadIdx.x;               // 0..127
    int bh = blockIdx.y;
    int b = bh >> 4, h = bh & 15;
    int t = blockIdx.x * 128 + tid;      // query row (always < 2048)

    const float* qrow = g_q + (((size_t)(b*TT + t))*HH + h) * DD;
    float qreg[64];
#pragma unroll
    for (int i = 0; i < 16; i++) {
        float4 v4 = ((const float4*)qrow)[i];
        qreg[4*i]   = v4.x; qreg[4*i+1] = v4.y;
        qreg[4*i+2] = v4.z; qreg[4*i+3] = v4.w;
    }

    float mx = -1e30f, l = 0.f;
    float acc[64];
#pragma unroll
    for (int d = 0; d < 64; d++) acc[d] = 0.f;

    int t_last = blockIdx.x * 128 + 127;

    for (int n0 = 0; n0 <= t_last; n0 += 64) {
        // Cooperative tile load: 64 keys x 64 floats = 1024 float4 per tensor.
        const float4* kbase = (const float4*)(g_k + (((size_t)(b*TT + n0))*HH + h) * DD);
        const float4* vbase = (const float4*)(g_v + (((size_t)(b*TT + n0))*HH + h) * DD);
#pragma unroll
        for (int i = 0; i < 8; i++) {
            int idx = tid + i * 128;     // 0..1023
            int kr = idx >> 4;           // key row in tile
            int d4 = idx & 15;
            ((float4*)&Ks[kr][0])[d4] = kbase[(size_t)kr * (HH*DD/4) + d4];
            ((float4*)&Vs[kr][0])[d4] = vbase[(size_t)kr * (HH*DD/4) + d4];
        }
        __syncthreads();

        int jend = t - n0 + 1;
        if (jend > 64) jend = 64;
        for (int j = 0; j < jend; j++) {
            float s = 0.f;
            const float4* kr4 = (const float4*)&Ks[j][0];
#pragma unroll
            for (int d4 = 0; d4 < 16; d4++) {
                float4 kv = kr4[d4];
                s += qreg[4*d4]*kv.x + qreg[4*d4+1]*kv.y
                   + qreg[4*d4+2]*kv.z + qreg[4*d4+3]*kv.w;
            }
            s *= 0.125f;   // 1/sqrt(64)

            if (s > mx) {
                float corr = __expf(mx - s);
                mx = s;
                l *= corr;
#pragma unroll
                for (int d = 0; d < 64; d++) acc[d] *= corr;
            }
            float p = __expf(s - mx);
            l += p;
            const float4* vr4 = (const float4*)&Vs[j][0];
#pragma unroll
            for (int d4 = 0; d4 < 16; d4++) {
                float4 vv = vr4[d4];
                acc[4*d4]   += p * vv.x;
                acc[4*d4+1] += p * vv.y;
                acc[4*d4+2] += p * vv.z;
                acc[4*d4+3] += p * vv.w;
            }
        }
        __syncthreads();
    }

    float invl = 1.f / l;
    float* yrow = g_att + ((size_t)(b*TT + t))*CC + h*DD;
#pragma unroll
    for (int d4 = 0; d4 < 16; d4++) {
        float4 o;
        o.x = acc[4*d4]   * invl;
        o.y = acc[4*d4+1] * invl;
        o.z = acc[4*d4+2] * invl;
        o.w = acc[4*d4+3] * invl;
        ((float4*)yrow)[d4] = o;
    }
}

// ---------------------------------------------------------------------------
extern "C" void kernel_launch(void* const* d_in, const int* in_sizes, int n_in,
                              void* d_out, int out_size)
{
    const float* x  = (const float*)d_in[0];
    const float* Wq = (const float*)d_in[1];
    const float* bq = (const float*)d_in[2];
    const float* Wk = (const float*)d_in[3];
    const float* bk = (const float*)d_in[4];
    const float* Wv = (const float*)d_in[5];
    const float* bv = (const float*)d_in[6];
    const float* Wp = (const float*)d_in[7];
    const float* bp = (const float*)d_in[8];
    float* out = (float*)d_out;

    // 1. QKV projections (3 GEMMs via gridDim.z)
    dim3 gemm_grid(1024/128, 4096/128, 3);   // (8, 32, 3)
    sgemm_qkv_kernel<<<gemm_grid, 256>>>(x, Wq, bq, Wk, bk, Wv, bv);

    // 2. RoPE in-place on q, k
    int rope_threads = 2 * NPAIR;
    rope_kernel<<<(rope_threads + 255) / 256, 256>>>();

    // 3. Causal attention -> g_att
    dim3 attn_grid(TT/128, BB*HH);           // (16, 32)
    attn_kernel<<<attn_grid, 128>>>();

    // 4. Output projection -> d_out
    dim3 proj_grid(1024/128, 4096/128);
    sgemm_proj_kernel<<<proj_grid, 256>>>(Wp, bp, out);
}